// round 12
// baseline (speedup 1.0000x reference)
#include <cuda_runtime.h>
#include <math.h>

#define H    16
#define L    2048
#define DK   64
#define RB   32
#define ROWS 8
#define SPAD 8           // S row = 8 floats (2 swizzled 16B quad-groups, no pad)

// Scratch (device globals: no allocs allowed)
__device__ float g_C[H * L * RB];
__device__ float g_B[H * L * RB];

// ---- f32x2 packed helpers --------------------------------------------------
typedef unsigned long long u64;

__device__ __forceinline__ u64 pk(float lo, float hi) {
    u64 r; asm("mov.b64 %0, {%1, %2};" : "=l"(r) : "f"(lo), "f"(hi)); return r;
}
__device__ __forceinline__ void fma2(u64 &acc, u64 a, u64 b) {
    asm("fma.rn.f32x2 %0, %1, %2, %0;" : "+l"(acc) : "l"(a), "l"(b));
}
__device__ __forceinline__ float2 upk(u64 v) {
    float2 r; asm("mov.b64 {%0, %1}, %2;" : "=f"(r.x), "=f"(r.y) : "l"(v)); return r;
}
__device__ __forceinline__ void cp16(float* dst_smem, const float* src) {
    unsigned s = (unsigned)__cvta_generic_to_shared(dst_smem);
    asm volatile("cp.async.cg.shared.global [%0], [%1], 16;" :: "r"(s), "l"(src));
}
__device__ __forceinline__ void cp_commit() {
    asm volatile("cp.async.commit_group;");
}
__device__ __forceinline__ void cp_wait0() {
    asm volatile("cp.async.wait_group 0;");
}

// ---------------------------------------------------------------------------
// Kernel 1: projections (unchanged from R11).
// ---------------------------------------------------------------------------
__global__ __launch_bounds__(256)
void proj_kernel(const float* __restrict__ q,
                 const float* __restrict__ Wa, const float* __restrict__ ba,
                 const float* __restrict__ Wb, const float* __restrict__ bb) {
    __shared__ float Ut[DK * DK];   // [k][o]
    __shared__ float us[DK];
    __shared__ float qs[64 * DK];   // [r][k]
    int tid = threadIdx.x;
    int row0 = blockIdx.x * 64;

    for (int i = tid; i < DK * DK; i += 256) {
        int o = i >> 6, k = i & 63;
        float u;
        if (o < 32) u = 32.f * (Wa[(2 * o) * DK + k] + Wa[(2 * o + 1) * DK + k]);
        else        u = Wb[(o - 32) * DK + k];
        Ut[k * DK + o] = u;
    }
    if (tid < DK)
        us[tid] = (tid < 32) ? 32.f * (ba[2 * tid] + ba[2 * tid + 1]) : bb[tid - 32];
    {
        float4* q4 = (float4*)qs;  const float4* g4 = (const float4*)(q + (size_t)row0 * DK);
        for (int i = tid; i < 64 * DK / 4; i += 256) q4[i] = g4[i];
    }
    __syncthreads();

    int tr = tid >> 4, tc = tid & 15;
    float acc[4][4] = {};
#pragma unroll 8
    for (int k = 0; k < DK; k++) {
        float4 u = *(const float4*)(Ut + k * DK + 4 * tc);
        float qv[4];
#pragma unroll
        for (int ri = 0; ri < 4; ri++) qv[ri] = qs[(4 * tr + ri) * DK + k];
#pragma unroll
        for (int ri = 0; ri < 4; ri++) {
            acc[ri][0] += qv[ri] * u.x;  acc[ri][1] += qv[ri] * u.y;
            acc[ri][2] += qv[ri] * u.z;  acc[ri][3] += qv[ri] * u.w;
        }
    }
    float4 ub = *(const float4*)(us + 4 * tc);
#pragma unroll
    for (int ri = 0; ri < 4; ri++) {
        int row = row0 + 4 * tr + ri;
        float4 o = make_float4(acc[ri][0] + ub.x, acc[ri][1] + ub.y,
                               acc[ri][2] + ub.z, acc[ri][3] + ub.w);
        if (tc < 8) *(float4*)(g_C + (size_t)row * RB + 4 * tc)        = o;
        else        *(float4*)(g_B + (size_t)row * RB + (4 * tc - 32)) = o;
    }
}

// ---------------------------------------------------------------------------
// Kernel 2: fused attention. CTA = (head, 8-row tile), 256 threads, 2 CTAs/SM.
// S[j] = 8 floats in 2 quad-groups; group g at quad 4*(g ^ ((j>>2)&1)).
//  Phase 1: S = C @ B^T; 128-j chunks, double-buffered cp.async.
//  Phase 2: 3-pass softmax, warp per row; inv in Cs[r].
//  Phase 3: E @ v; warp = 2 j, thread = 8 rows x 4 d; v LDG.128 prefetch.
//  Epilogue: 16-part reduction in dead S.
// ---------------------------------------------------------------------------
__global__ __launch_bounds__(256, 2)
void attn_kernel(const float* __restrict__ v,
                 float* __restrict__ out,    // [H, L, DK]
                 float* __restrict__ attn) { // [H, L, L]
    extern __shared__ float sm[];
    float* S   = sm;                  // L * SPAD = 16384 floats
    float* Cs  = S + L * SPAD;        // 8 * 32   = 256 (later inv[8])
    float* buf = Cs + ROWS * RB;      // 2 x 4096 floats (B chunk double-buffer)

    int tid  = threadIdx.x;
    int lane = tid & 31, w = tid >> 5;          // 8 warps
    int head = blockIdx.x >> 8;                 // 256 row-tiles per head
    int rt   = blockIdx.x & 255;
    int row0 = rt * ROWS;

    const float* gB = g_B + (size_t)head * L * RB;

    // stage chunk 0 (128 j x 32 floats)
    {
#pragma unroll
        for (int t = 0; t < 4; t++) {
            int idx4 = tid + 256 * t;              // float4 index, 0..1023
            int j = idx4 >> 3, i = idx4 & 7;
            cp16(buf + j * RB + 4 * (i ^ (j & 7)), gB + (size_t)j * RB + 4 * i);
        }
        cp_commit();
    }

    // C tile for these 8 rows (64 float4)
    if (tid < 64)
        ((float4*)Cs)[tid] =
            ((const float4*)(g_C + (size_t)(head * L + row0) * RB))[tid];

    // ---- Phase 1: S[j][r] = sum_m C[r][m] * B[j][m] --------------------------
    int jq = tid & 63, rq = tid >> 6;            // thread: j in {jq, jq+64}, rows {2rq, 2rq+1}
    for (int c = 0; c < 16; c++) {
        cp_wait0();
        __syncthreads();                          // chunk c visible; other buffer free
        if (c < 15) {
            float* bn = buf + ((c + 1) & 1) * 4096;
            const float* gn = gB + (size_t)(c + 1) * 128 * RB;
#pragma unroll
            for (int t = 0; t < 4; t++) {
                int idx4 = tid + 256 * t;
                int j = idx4 >> 3, i = idx4 & 7;
                cp16(bn + j * RB + 4 * (i ^ (j & 7)), gn + (size_t)j * RB + 4 * i);
            }
            cp_commit();
        }
        const float* bc = buf + (c & 1) * 4096;
        int j0 = c * 128;
        const float* cr0 = Cs + (2 * rq) * RB;
        const float* cr1 = cr0 + RB;
        u64 aA0 = 0, aA1 = 0, aB0 = 0, aB1 = 0;
#pragma unroll
        for (int i = 0; i < 8; i++) {
            ulonglong2 ca = *(const ulonglong2*)(cr0 + 4 * i);   // bcast
            ulonglong2 cb = *(const ulonglong2*)(cr1 + 4 * i);   // bcast
            int sw = 4 * (i ^ (jq & 7));
            ulonglong2 bA = *(const ulonglong2*)(bc + jq * RB + sw);
            ulonglong2 bB = *(const ulonglong2*)(bc + (jq + 64) * RB + sw);
            fma2(aA0, ca.x, bA.x);  fma2(aA0, ca.y, bA.y);
            fma2(aA1, cb.x, bA.x);  fma2(aA1, cb.y, bA.y);
            fma2(aB0, ca.x, bB.x);  fma2(aB0, ca.y, bB.y);
            fma2(aB1, cb.x, bB.x);  fma2(aB1, cb.y, bB.y);
        }
        int s  = (jq >> 2) & 1;                  // same for jq and jq+64
        int gg = rq >> 1;
        int off = 4 * (gg ^ s) + 2 * (rq & 1);
        {
            float2 t0 = upk(aA0), t1 = upk(aA1);
            *(float2*)(S + (size_t)(j0 + jq) * SPAD + off) =
                make_float2(t0.x + t0.y, t1.x + t1.y);
        }
        {
            float2 t0 = upk(aB0), t1 = upk(aB1);
            *(float2*)(S + (size_t)(j0 + jq + 64) * SPAD + off) =
                make_float2(t0.x + t0.y, t1.x + t1.y);
        }
    }
    __syncthreads();

    // ---- Phase 2: softmax, warp w owns row w (3 passes, marching ptrs) ------
    {
        int r = w, g = r >> 2, e = r & 3;
        int off = 4 * (g ^ ((lane >> 2) & 1)) + e;   // per-lane constant slot
        const float* p0 = S + lane * SPAD + off;
        float mx = -1e30f;
#pragma unroll
        for (int k = 0; k < 64; k++) { mx = fmaxf(mx, *p0); p0 += 32 * SPAD; }
#pragma unroll
        for (int o = 16; o > 0; o >>= 1) mx = fmaxf(mx, __shfl_xor_sync(0xffffffffu, mx, o));
        float* p1 = S + lane * SPAD + off;
        float sum = 0.f;
#pragma unroll
        for (int k = 0; k < 64; k++) {
            float ee = __expf(*p1 - mx);
            *p1 = ee;                     // keep unnormalized E
            sum += ee;
            p1 += 32 * SPAD;
        }
#pragma unroll
        for (int o = 16; o > 0; o >>= 1) sum += __shfl_xor_sync(0xffffffffu, sum, o);
        float inv = 1.f / sum;
        if (lane == 0) Cs[r] = inv;       // Cs no longer needed as C
        const float* p2 = S + lane * SPAD + off;
        float* ar = attn + (size_t)(head * L + row0 + r) * L + lane;
#pragma unroll
        for (int k = 0; k < 64; k++) {
            *ar = *p2 * inv;              // dense_attn (coalesced STG)
            p2 += 32 * SPAD;  ar += 32;
        }
    }
    __syncthreads();

    // ---- Phase 3: out = E @ v (v LDG prefetch dist 2) -----------------------
    int sub = (tid >> 4) & 1;            // which of the warp's 2 j
    int dq  = tid & 15;                  // d quad: d = 4dq..4dq+3
    const float* gv = v + (size_t)head * L * DK;
    u64 a3[4][4];                        // [row-pair][d-component]
#pragma unroll
    for (int rp = 0; rp < 4; rp++)
#pragma unroll
        for (int di = 0; di < 4; di++) a3[rp][di] = 0ull;

    int jbase = w * 256 + sub;
    const float* vp  = gv + (size_t)jbase * DK + 4 * dq;
    const float* vpn = vp + 4 * DK;                     // t+2 prefetch stream
    const float* Sjp = S + (size_t)jbase * SPAD;
    float4 v4  = *(const float4*)vp;
    float4 v4b = *(const float4*)(vp + 2 * DK);

    for (int gi = 0; gi < 64; gi++) {
        int s = gi & 1;                   // (j>>2)&1 constant over this pair
        int o0 = 4 * s, o1 = 4 - o0;
#pragma unroll
        for (int t2 = 0; t2 < 2; t2++) {
            int t = 2 * gi + t2;
            float4 v4c = v4b;
            if (t < 126) v4c = *(const float4*)vpn;
            vpn += 2 * DK;
            ulonglong2 P0 = *(const ulonglong2*)(Sjp + o0);  // rows 0-3
            ulonglong2 P1 = *(const ulonglong2*)(Sjp + o1);  // rows 4-7
            Sjp += 2 * SPAD;
            u64 vv0 = pk(v4.x, v4.x), vv1 = pk(v4.y, v4.y);
            u64 vv2 = pk(v4.z, v4.z), vv3 = pk(v4.w, v4.w);
            fma2(a3[0][0], P0.x, vv0); fma2(a3[0][1], P0.x, vv1);
            fma2(a3[0][2], P0.x, vv2); fma2(a3[0][3], P0.x, vv3);
            fma2(a3[1][0], P0.y, vv0); fma2(a3[1][1], P0.y, vv1);
            fma2(a3[1][2], P0.y, vv2); fma2(a3[1][3], P0.y, vv3);
            fma2(a3[2][0], P1.x, vv0); fma2(a3[2][1], P1.x, vv1);
            fma2(a3[2][2], P1.x, vv2); fma2(a3[2][3], P1.x, vv3);
            fma2(a3[3][0], P1.y, vv0); fma2(a3[3][1], P1.y, vv1);
            fma2(a3[3][2], P1.y, vv2); fma2(a3[3][3], P1.y, vv3);
            v4 = v4b;  v4b = v4c;
        }
    }

    // ---- Epilogue: 16-part reduction; reuse dead S region -------------------
    __syncthreads();                      // all threads done reading S
    {
        float* red = S;                   // [part][r][d] = part*512 + r*64 + d
        int part = w * 2 + sub;
#pragma unroll
        for (int rp = 0; rp < 4; rp++) {
            float2 e0 = upk(a3[rp][0]), e1 = upk(a3[rp][1]);
            float2 e2 = upk(a3[rp][2]), e3 = upk(a3[rp][3]);
            *(float4*)(red + part * 512 + (2 * rp)     * 64 + 4 * dq) =
                make_float4(e0.x, e1.x, e2.x, e3.x);
            *(float4*)(red + part * 512 + (2 * rp + 1) * 64 + 4 * dq) =
                make_float4(e0.y, e1.y, e2.y, e3.y);
        }
        __syncthreads();
        int oq = tid >> 1, ph = tid & 1;          // 128 float4 outputs, 2 thr each
        int r = oq >> 4, dq2 = oq & 15;
        float4 s4 = make_float4(0.f, 0.f, 0.f, 0.f);
        const float* rp2 = red + ph * 8 * 512 + r * 64 + 4 * dq2;
#pragma unroll
        for (int p = 0; p < 8; p++) {
            float4 t4 = *(const float4*)rp2;
            s4.x += t4.x; s4.y += t4.y; s4.z += t4.z; s4.w += t4.w;
            rp2 += 512;
        }
        s4.x += __shfl_xor_sync(0xffffffffu, s4.x, 1);
        s4.y += __shfl_xor_sync(0xffffffffu, s4.y, 1);
        s4.z += __shfl_xor_sync(0xffffffffu, s4.z, 1);
        s4.w += __shfl_xor_sync(0xffffffffu, s4.w, 1);
        if (ph == 0) {
            float iv = Cs[r];
            *(float4*)(out + (size_t)(head * L + row0 + r) * DK + 4 * dq2) =
                make_float4(s4.x * iv, s4.y * iv, s4.z * iv, s4.w * iv);
        }
    }
}

// ---------------------------------------------------------------------------
extern "C" void kernel_launch(void* const* d_in, const int* in_sizes, int n_in,
                              void* d_out, int out_size) {
    const float* q  = (const float*)d_in[0];
    const float* v  = (const float*)d_in[1];
    const float* Wa = (const float*)d_in[2];
    const float* ba = (const float*)d_in[3];
    const float* Wb = (const float*)d_in[4];
    const float* bb = (const float*)d_in[5];

    float* out  = (float*)d_out;                 // [H, L, DK]
    float* attn = out + (size_t)H * L * DK;      // [H, L, L]

    const int smem = (L * SPAD + ROWS * RB + 2 * 4096) * 4;   // 99328 B
    cudaFuncSetAttribute(attn_kernel, cudaFuncAttributeMaxDynamicSharedMemorySize, smem);

    proj_kernel<<<H * L / 64, 256>>>(q, Wa, ba, Wb, bb);
    attn_kernel<<<H * (L / ROWS), 256, smem>>>(v, out, attn);
}